// round 1
// baseline (speedup 1.0000x reference)
#include <cuda_runtime.h>
#include <cstdint>

// Problem constants
#define BSZ 2
#define NN  4096
#define JJ  3
#define CC  32
#define KO  32                  // output channels
#define MJ  (NN*JJ)             // 12288 reduction length
#define BM  128                 // rows per block tile
#define BKT 32                  // K-slice per smem tile
#define SPLITS 8
#define ITERS ((MJ/BKT)/SPLITS) // 48

// scratch: t[b][mj][k]  (3 MB)
__device__ float g_t[BSZ * MJ * KO];

// ---------------------------------------------------------------------------
// Kernel 0: out[b][k][n] = bias[k]
// ---------------------------------------------------------------------------
__global__ void init_out_kernel(float* __restrict__ out, const float* __restrict__ bias) {
    int i = blockIdx.x * blockDim.x + threadIdx.x;
    if (i < BSZ * KO * NN) out[i] = bias[(i >> 12) & 31];   // NN = 2^12
}

// ---------------------------------------------------------------------------
// Kernel 1: t[b][m*3+j][k] = sum_c conv_w[k][j*CC+c] * x[b][m][c]
// tid layout == t layout:  tid = ((b*NN+m)*3 + j)*32 + k
// ---------------------------------------------------------------------------
__global__ void precompute_t_kernel(const float* __restrict__ x,
                                    const float* __restrict__ cw) {
    int tid = blockIdx.x * blockDim.x + threadIdx.x;     // exact grid, no bound
    int k  = tid & 31;
    int j  = (tid >> 5) % 3;
    int bm = tid / 96;                                   // b*NN + m
    const float* xr = x  + (size_t)bm * CC;
    const float* wr = cw + k * (JJ * CC) + j * CC;
    float s = 0.f;
#pragma unroll
    for (int c = 0; c < CC; ++c) s = fmaf(wr[c], xr[c], s);
    g_t[tid] = s;
}

// ---------------------------------------------------------------------------
// Kernel 2: split-K GEMM.  out[b][k][n] += sum_mj W[b][n][mj] * t[b][mj][k]
// Block: 256 threads; tile BM=128 rows x 32 cols over BKT=32 K-slices.
// Warp grid 4x2 (warp tile 32x16), thread tile 4x4.
// ---------------------------------------------------------------------------
__global__ __launch_bounds__(256) void gemm_kernel(const float* __restrict__ W,
                                                   float* __restrict__ out) {
    __shared__ float Wsh[BM * 33];      // stride-33 pad: conflict-free a-frag reads
    __shared__ float Tsh[BKT * KO];     // 32x32

    const int b   = blockIdx.z;
    const int n0  = blockIdx.x * BM;
    const int kk0 = blockIdx.y * (ITERS * BKT);

    const int tid  = threadIdx.x;
    const int warp = tid >> 5, lane = tid & 31;
    const int wr_  = warp & 3, wc_ = warp >> 2;     // 4 warp-rows x 2 warp-cols
    const int ty   = lane >> 2, tx = lane & 3;
    const int row0 = wr_ * 32 + ty * 4;
    const int col0 = wc_ * 16 + tx * 4;

    const float* Wbase = W   + ((size_t)(b * NN + n0)) * MJ + kk0;
    const float* Tbase = g_t + ((size_t)b * MJ + kk0) * KO;

    // cooperative-load coordinates: 1024 float4 per W tile, 4 per thread
    const int lr = tid >> 3;            // row group 0..31 (+q*32)
    const int lc = (tid & 7) * 4;       // float4 column offset

    float acc[4][4] = {};

    float4 wreg[4], treg;
#pragma unroll
    for (int q = 0; q < 4; ++q)
        wreg[q] = *(const float4*)(Wbase + (size_t)(lr + q * 32) * MJ + lc);
    treg = *(const float4*)(Tbase + tid * 4);

    for (int it = 0; it < ITERS; ++it) {
        __syncthreads();                 // prior compute done before smem overwrite
#pragma unroll
        for (int q = 0; q < 4; ++q) {
            int r = lr + q * 32;
            Wsh[r * 33 + lc + 0] = wreg[q].x;
            Wsh[r * 33 + lc + 1] = wreg[q].y;
            Wsh[r * 33 + lc + 2] = wreg[q].z;
            Wsh[r * 33 + lc + 3] = wreg[q].w;
        }
        *(float4*)(Tsh + tid * 4) = treg;
        __syncthreads();

        if (it + 1 < ITERS) {            // prefetch next tile into registers
            const float* wp = Wbase + (it + 1) * BKT;
#pragma unroll
            for (int q = 0; q < 4; ++q)
                wreg[q] = *(const float4*)(wp + (size_t)(lr + q * 32) * MJ + lc);
            treg = *(const float4*)(Tbase + (it + 1) * (BKT * KO) + tid * 4);
        }

#pragma unroll
        for (int kk = 0; kk < BKT; ++kk) {
            float a0 = Wsh[(row0 + 0) * 33 + kk];
            float a1 = Wsh[(row0 + 1) * 33 + kk];
            float a2 = Wsh[(row0 + 2) * 33 + kk];
            float a3 = Wsh[(row0 + 3) * 33 + kk];
            float4 bv = *(const float4*)(Tsh + kk * KO + col0);
            acc[0][0] = fmaf(a0, bv.x, acc[0][0]);
            acc[0][1] = fmaf(a0, bv.y, acc[0][1]);
            acc[0][2] = fmaf(a0, bv.z, acc[0][2]);
            acc[0][3] = fmaf(a0, bv.w, acc[0][3]);
            acc[1][0] = fmaf(a1, bv.x, acc[1][0]);
            acc[1][1] = fmaf(a1, bv.y, acc[1][1]);
            acc[1][2] = fmaf(a1, bv.z, acc[1][2]);
            acc[1][3] = fmaf(a1, bv.w, acc[1][3]);
            acc[2][0] = fmaf(a2, bv.x, acc[2][0]);
            acc[2][1] = fmaf(a2, bv.y, acc[2][1]);
            acc[2][2] = fmaf(a2, bv.z, acc[2][2]);
            acc[2][3] = fmaf(a2, bv.w, acc[2][3]);
            acc[3][0] = fmaf(a3, bv.x, acc[3][0]);
            acc[3][1] = fmaf(a3, bv.y, acc[3][1]);
            acc[3][2] = fmaf(a3, bv.z, acc[3][2]);
            acc[3][3] = fmaf(a3, bv.w, acc[3][3]);
        }
    }

    // epilogue: split-K accumulate into out[b][k][n]
#pragma unroll
    for (int i = 0; i < 4; ++i) {
        int n = n0 + row0 + i;
#pragma unroll
        for (int jx = 0; jx < 4; ++jx) {
            int kcol = col0 + jx;
            atomicAdd(out + ((size_t)b * KO + kcol) * NN + n, acc[i][jx]);
        }
    }
}

// ---------------------------------------------------------------------------
extern "C" void kernel_launch(void* const* d_in, const int* in_sizes, int n_in,
                              void* d_out, int out_size) {
    const float* W  = (const float*)d_in[0];
    const float* x  = (const float*)d_in[1];
    const float* cw = (const float*)d_in[2];
    const float* cb = (const float*)d_in[3];
    float* out = (float*)d_out;

    init_out_kernel<<<(BSZ * KO * NN + 255) / 256, 256>>>(out, cb);
    precompute_t_kernel<<<(BSZ * MJ * KO) / 256, 256>>>(x, cw);

    dim3 grid(NN / BM, SPLITS, BSZ);
    gemm_kernel<<<grid, 256>>>(W, out);
}

// round 2
// speedup vs baseline: 1.4983x; 1.4983x over previous
#include <cuda_runtime.h>
#include <cstdint>

#define BSZ 2
#define NN  4096
#define JJ  3
#define CC  32
#define KO  32
#define MJ  (NN*JJ)             // 12288
#define BM  128
#define BKT 32
#define SPLITS 8
#define ITERS ((MJ/BKT)/SPLITS) // 48

#define WS  36                  // padded smem stride (bank = (4r+c)%32, conflict-free frags)

__device__ float g_t[BSZ * MJ * KO];   // t[b][mj][k], tf32-rounded

__device__ __forceinline__ uint32_t f2tf32(float f) {
    uint32_t o;
    asm("cvt.rna.tf32.f32 %0, %1;" : "=r"(o) : "f"(f));
    return o;
}

// ---------------------------------------------------------------------------
__global__ void init_out_kernel(float* __restrict__ out, const float* __restrict__ bias) {
    int i = blockIdx.x * blockDim.x + threadIdx.x;
    if (i < BSZ * KO * NN) out[i] = bias[(i >> 12) & 31];
}

// t[b][m*3+j][k] = sum_c conv_w[k][j*CC+c] * x[b][m][c]   (tf32-rounded)
__global__ void precompute_t_kernel(const float* __restrict__ x,
                                    const float* __restrict__ cw) {
    int tid = blockIdx.x * blockDim.x + threadIdx.x;
    int k  = tid & 31;
    int j  = (tid >> 5) % 3;
    int bm = tid / 96;
    const float* xr = x  + (size_t)bm * CC;
    const float* wr = cw + k * (JJ * CC) + j * CC;
    float s = 0.f;
#pragma unroll
    for (int c = 0; c < CC; ++c) s = fmaf(wr[c], xr[c], s);
    ((uint32_t*)g_t)[tid] = f2tf32(s);
}

// ---------------------------------------------------------------------------
// Split-K tf32 tensor-core GEMM: out[b][k][n] += sum_mj W[b][n][mj]*t[b][mj][k]
// Block 256 thr / 8 warps. Tile BM=128 x KO=32, BK=32. Warp w: rows w*16..+15.
// ---------------------------------------------------------------------------
__global__ __launch_bounds__(256) void gemm_kernel(const float* __restrict__ W,
                                                   float* __restrict__ out) {
    __shared__ uint32_t Wsh[BM * WS];     // A tile (row-major, tf32 bits)
    __shared__ uint32_t Tsh[KO * WS];     // B tile transposed: Tsh[ko][kk]

    const int b   = blockIdx.z;
    const int n0  = blockIdx.x * BM;
    const int kk0 = blockIdx.y * (ITERS * BKT);

    const int tid  = threadIdx.x;
    const int warp = tid >> 5, lane = tid & 31;
    const int lg   = lane >> 2, lt = lane & 3;     // groupID, thread-in-group
    const int row0 = warp * 16;

    const float* Wbase = W   + ((size_t)(b * NN + n0)) * MJ + kk0;
    const float* Tbase = g_t + ((size_t)b * MJ + kk0) * KO;

    // cooperative W load: 1024 float4 per tile, 4 per thread
    const int wlr = tid >> 3;              // 0..31 (+q*32)
    const int wlc = (tid & 7) * 4;
    // cooperative t load: 256 float4, 1 per thread (reads [kk][ko], writes [ko][kk])
    const int tko = (tid & 7) * 4;
    const int tkk = tid >> 3;

    float acc[4][4];
#pragma unroll
    for (int i = 0; i < 4; ++i)
#pragma unroll
        for (int j = 0; j < 4; ++j) acc[i][j] = 0.f;

    float4 wreg[4], treg;
#pragma unroll
    for (int q = 0; q < 4; ++q)
        wreg[q] = *(const float4*)(Wbase + (size_t)(wlr + q * 32) * MJ + wlc);
    treg = *(const float4*)(Tbase + tid * 4);

    for (int it = 0; it < ITERS; ++it) {
        __syncthreads();
#pragma unroll
        for (int q = 0; q < 4; ++q) {
            uint4 v = { f2tf32(wreg[q].x), f2tf32(wreg[q].y),
                        f2tf32(wreg[q].z), f2tf32(wreg[q].w) };
            *(uint4*)(Wsh + (wlr + q * 32) * WS + wlc) = v;
        }
        // t already tf32 bits; transpose-scatter
        Tsh[(tko + 0) * WS + tkk] = __float_as_uint(treg.x);
        Tsh[(tko + 1) * WS + tkk] = __float_as_uint(treg.y);
        Tsh[(tko + 2) * WS + tkk] = __float_as_uint(treg.z);
        Tsh[(tko + 3) * WS + tkk] = __float_as_uint(treg.w);
        __syncthreads();

        if (it + 1 < ITERS) {
            const float* wp = Wbase + (it + 1) * BKT;
#pragma unroll
            for (int q = 0; q < 4; ++q)
                wreg[q] = *(const float4*)(wp + (size_t)(wlr + q * 32) * MJ + wlc);
            treg = *(const float4*)(Tbase + (it + 1) * (BKT * KO) + tid * 4);
        }

#pragma unroll
        for (int s = 0; s < 4; ++s) {                 // k8 steps within BK=32
            const int kc = s * 8;
            uint32_t a0 = Wsh[(row0 + lg)     * WS + kc + lt];
            uint32_t a1 = Wsh[(row0 + lg + 8) * WS + kc + lt];
            uint32_t a2 = Wsh[(row0 + lg)     * WS + kc + lt + 4];
            uint32_t a3 = Wsh[(row0 + lg + 8) * WS + kc + lt + 4];
#pragma unroll
            for (int nt = 0; nt < 4; ++nt) {          // n 0..31 in 8-col tiles
                uint32_t b0 = Tsh[(nt * 8 + lg) * WS + kc + lt];
                uint32_t b1 = Tsh[(nt * 8 + lg) * WS + kc + lt + 4];
                asm volatile(
                    "mma.sync.aligned.m16n8k8.row.col.f32.tf32.tf32.f32 "
                    "{%0,%1,%2,%3}, {%4,%5,%6,%7}, {%8,%9}, {%0,%1,%2,%3};"
                    : "+f"(acc[nt][0]), "+f"(acc[nt][1]),
                      "+f"(acc[nt][2]), "+f"(acc[nt][3])
                    : "r"(a0), "r"(a1), "r"(a2), "r"(a3), "r"(b0), "r"(b1));
            }
        }
    }

    // ---- epilogue: stage tile in smem (stride 33), coalesced atomics ----
    __syncthreads();
    float* stg = (float*)Wsh;                          // 128*33 <= 128*36 ✓
#pragma unroll
    for (int nt = 0; nt < 4; ++nt) {
        int col = nt * 8 + lt * 2;
        stg[(row0 + lg)     * 33 + col]     = acc[nt][0];
        stg[(row0 + lg)     * 33 + col + 1] = acc[nt][1];
        stg[(row0 + lg + 8) * 33 + col]     = acc[nt][2];
        stg[(row0 + lg + 8) * 33 + col + 1] = acc[nt][3];
    }
    __syncthreads();
#pragma unroll
    for (int p = 0; p < 16; ++p) {
        int idx = p * 256 + tid;           // 4096 outputs
        int nl = idx & 127, k = idx >> 7;
        atomicAdd(out + ((size_t)b * KO + k) * NN + n0 + nl, stg[nl * 33 + k]);
    }
}

// ---------------------------------------------------------------------------
extern "C" void kernel_launch(void* const* d_in, const int* in_sizes, int n_in,
                              void* d_out, int out_size) {
    const float* W  = (const float*)d_in[0];
    const float* x  = (const float*)d_in[1];
    const float* cw = (const float*)d_in[2];
    const float* cb = (const float*)d_in[3];
    float* out = (float*)d_out;

    init_out_kernel<<<(BSZ * KO * NN + 255) / 256, 256>>>(out, cb);
    precompute_t_kernel<<<(BSZ * MJ * KO) / 256, 256>>>(x, cw);

    dim3 grid(NN / BM, SPLITS, BSZ);
    gemm_kernel<<<grid, 256>>>(W, out);
}